// round 3
// baseline (speedup 1.0000x reference)
#include <cuda_runtime.h>
#include <cstdint>
#include <cstddef>

// GraphAttentionLayer: N=12288, IN_F=256, OUT_F=128
// out = [h_prime (N*128 f32) | attention (N*N f32)]

constexpr int N_  = 12288;
constexpr int INF = 256;
constexpr int OF  = 128;
constexpr float SLOPE = 0.2f;

constexpr int RT = 64;              // rows per CTA in main kernel
constexpr int CT = 32;              // j-tile width
constexpr int NSPLIT = 4;           // j-dimension split for load balance
constexpr int JSEG = N_ / NSPLIT;   // 3072
constexpr int NTILE = JSEG / CT;    // 96

// ---- scratch (static device arrays; no allocation allowed) ----
__device__ float g_ht[(size_t)N_ * OF];              // h @ W               6 MB
__device__ float g_src[N_];
__device__ float g_tgt[N_];
__device__ float g_Tmax;
__device__ float g_Zp[NSPLIT * N_];                  // partial Z per split
__device__ float g_hp[(size_t)NSPLIT * N_ * OF];     // partial h_prime    25 MB
__device__ float g_invZ[N_];

// ---- packed fp32x2 helpers (Blackwell; PTX-only, ptxas won't auto-fuse) ----
__device__ __forceinline__ unsigned long long pk2(float x) {
    unsigned long long r;
    asm("mov.b64 %0, {%1, %1};" : "=l"(r) : "r"(__float_as_uint(x)));
    return r;
}
__device__ __forceinline__ void fma2(unsigned long long& d, unsigned long long a, unsigned long long b) {
    asm("fma.rn.f32x2 %0, %1, %2, %0;" : "+l"(d) : "l"(a), "l"(b));
}

// ============================================================
// Kernel 1: h_t = h @ W   (M=12288, K=256, N=128)
// ============================================================
__global__ __launch_bounds__(256) void k_ht(const float* __restrict__ h, const float* __restrict__ W) {
    __shared__ float As[64 * 32];    // 8 KB
    __shared__ float Bs[32 * 128];   // 16 KB
    const int t = threadIdx.x, tx = t & 31, ty = t >> 5;
    const int r0 = blockIdx.x * 64;
    float4 acc[8];
#pragma unroll
    for (int r = 0; r < 8; ++r) acc[r] = make_float4(0.f, 0.f, 0.f, 0.f);

    for (int k0 = 0; k0 < INF; k0 += 32) {
#pragma unroll
        for (int k = 0; k < 2; ++k) {
            int id = t + k * 256;               // 0..511 float4s
            int row = id >> 3, c4 = id & 7;
            reinterpret_cast<float4*>(As)[id] =
                *reinterpret_cast<const float4*>(h + (size_t)(r0 + row) * INF + k0 + c4 * 4);
        }
#pragma unroll
        for (int k = 0; k < 4; ++k) {
            int id = t + k * 256;               // 0..1023 float4s
            int row = id >> 5, c4 = id & 31;
            reinterpret_cast<float4*>(Bs)[id] =
                *reinterpret_cast<const float4*>(W + (size_t)(k0 + row) * OF + c4 * 4);
        }
        __syncthreads();
#pragma unroll
        for (int kk = 0; kk < 32; ++kk) {
            float4 b = reinterpret_cast<const float4*>(Bs)[kk * 32 + tx];
#pragma unroll
            for (int r = 0; r < 8; ++r) {
                float a = As[(ty * 8 + r) * 32 + kk];   // broadcast
                acc[r].x = fmaf(a, b.x, acc[r].x);
                acc[r].y = fmaf(a, b.y, acc[r].y);
                acc[r].z = fmaf(a, b.z, acc[r].z);
                acc[r].w = fmaf(a, b.w, acc[r].w);
            }
        }
        __syncthreads();
    }
#pragma unroll
    for (int r = 0; r < 8; ++r)
        *reinterpret_cast<float4*>(&g_ht[(size_t)(r0 + ty * 8 + r) * OF + tx * 4]) = acc[r];
}

// ============================================================
// Kernel 2: src = h_t @ a[:128], tgt = h_t @ a[128:]  (warp per row)
// ============================================================
__global__ __launch_bounds__(256) void k_srctgt(const float* __restrict__ a) {
    const int t = threadIdx.x;
    const int lane = t & 31;
    const int row = blockIdx.x * 8 + (t >> 5);
    float4 hv = *reinterpret_cast<const float4*>(g_ht + (size_t)row * OF + lane * 4);
    float4 a1 = *reinterpret_cast<const float4*>(a + lane * 4);
    float4 a2 = *reinterpret_cast<const float4*>(a + OF + lane * 4);
    float s1 = hv.x * a1.x + hv.y * a1.y + hv.z * a1.z + hv.w * a1.w;
    float s2 = hv.x * a2.x + hv.y * a2.y + hv.z * a2.z + hv.w * a2.w;
#pragma unroll
    for (int off = 16; off > 0; off >>= 1) {
        s1 += __shfl_xor_sync(0xffffffffu, s1, off);
        s2 += __shfl_xor_sync(0xffffffffu, s2, off);
    }
    if (lane == 0) { g_src[row] = s1; g_tgt[row] = s2; }
}

// ============================================================
// Kernel 3: Tmax = max(tgt)  (single block)
// ============================================================
__global__ void k_tmax() {
    __shared__ float red[1024];
    const int t = threadIdx.x;
    float m = -3.402823466e38f;
    for (int i = t; i < N_; i += 1024) m = fmaxf(m, g_tgt[i]);
    red[t] = m;
    __syncthreads();
    for (int s = 512; s > 0; s >>= 1) {
        if (t < s) red[t] = fmaxf(red[t], red[t + s]);
        __syncthreads();
    }
    if (t == 0) g_Tmax = red[0];
}

// ============================================================
// Kernel 4 (main): per 64-row block x 1/NSPLIT of columns:
//   p_ij = adj ? exp(lrelu(src_i+tgt_j) - M_i) : 0
//   Z_part[i]  = sum_j p_ij
//   hp_part[i] = sum_j p_ij * h_t[j]      (f32x2 packed FMA)
// M_i = lrelu(src_i + Tmax) upper-bounds every score (lrelu monotone),
// and softmax is shift-invariant, so normalization stays exact.
// ============================================================
__global__ __launch_bounds__(256, 2) void k_main(const int* __restrict__ adj) {
    __shared__ float ht_s[CT * OF];     // 16 KB
    __shared__ float p_s[RT * CT];      //  8 KB
    __shared__ float src_s[RT], m_s[RT], z_s[RT];

    const int t  = threadIdx.x;
    const int tx = t & 31, ty = t >> 5;
    const int rb = blockIdx.x >> 2;     // row block 0..191
    const int sp = blockIdx.x & 3;      // j split 0..3

    if (t < RT) {
        int rg = rb * RT + t;
        float sv = g_src[rg];
        src_s[t] = sv;
        float e = sv + g_Tmax;
        m_s[t] = (e >= 0.f) ? e : SLOPE * e;
        z_s[t] = 0.f;
    }
    __syncthreads();

    const int row_a = t >> 2, q = t & 3;     // phase-A mapping: 4 threads per row
    const float srcv = src_s[row_a];
    const float mv   = m_s[row_a];
    const size_t adj_row = (size_t)(rb * RT + row_a) * N_;

    unsigned long long acc[8][2];
#pragma unroll
    for (int r = 0; r < 8; ++r) { acc[r][0] = 0ull; acc[r][1] = 0ull; }
    const int ry = ty * 8;

    for (int tile = 0; tile < NTILE; ++tile) {
        const int j0 = sp * JSEG + tile * CT;

        // load h_t tile (32 x 128 fp32): 4 float4 per thread
#pragma unroll
        for (int k = 0; k < 4; ++k) {
            int id = t + k * 256;                            // 0..1023
            reinterpret_cast<float4*>(ht_s)[id] =
                reinterpret_cast<const float4*>(g_ht)[(size_t)j0 * 32 + id];
        }

        // phase A: adj -> p (8 j per thread, one row per 4-thread group)
        {
            const int4* ap = reinterpret_cast<const int4*>(adj + adj_row + j0 + q * 8);
            int4 a0 = ap[0], a1 = ap[1];
            float4 t0 = *reinterpret_cast<const float4*>(g_tgt + j0 + q * 8);
            float4 t1 = *reinterpret_cast<const float4*>(g_tgt + j0 + q * 8 + 4);
            float tv[8] = {t0.x, t0.y, t0.z, t0.w, t1.x, t1.y, t1.z, t1.w};
            int   av[8] = {a0.x, a0.y, a0.z, a0.w, a1.x, a1.y, a1.z, a1.w};
            float p[8];
            float zp = 0.f;
#pragma unroll
            for (int u = 0; u < 8; ++u) {
                float e  = srcv + tv[u];
                float lr = (e >= 0.f) ? e : SLOPE * e;
                float ex = __expf(lr - mv);
                p[u] = (av[u] > 0) ? ex : 0.f;
                zp += p[u];
            }
            *reinterpret_cast<float4*>(&p_s[row_a * CT + q * 8])     = make_float4(p[0], p[1], p[2], p[3]);
            *reinterpret_cast<float4*>(&p_s[row_a * CT + q * 8 + 4]) = make_float4(p[4], p[5], p[6], p[7]);
            zp += __shfl_xor_sync(0xffffffffu, zp, 1);
            zp += __shfl_xor_sync(0xffffffffu, zp, 2);
            if (q == 0) z_s[row_a] += zp;    // single writer per row
        }
        __syncthreads();

        // phase B: acc[8 rows][4 cols] += p * h_t  via packed f32x2 FMAs
        const ulonglong2* ht2 = reinterpret_cast<const ulonglong2*>(ht_s);
        const float4* p4 = reinterpret_cast<const float4*>(p_s);
#pragma unroll
        for (int j4 = 0; j4 < CT / 4; ++j4) {
            ulonglong2 h0 = ht2[(j4 * 4 + 0) * 32 + tx];
            ulonglong2 h1 = ht2[(j4 * 4 + 1) * 32 + tx];
            ulonglong2 h2 = ht2[(j4 * 4 + 2) * 32 + tx];
            ulonglong2 h3 = ht2[(j4 * 4 + 3) * 32 + tx];
#pragma unroll
            for (int r = 0; r < 8; ++r) {
                float4 pv = p4[(ry + r) * (CT / 4) + j4];   // broadcast LDS
                unsigned long long pp;
                pp = pk2(pv.x); fma2(acc[r][0], pp, h0.x); fma2(acc[r][1], pp, h0.y);
                pp = pk2(pv.y); fma2(acc[r][0], pp, h1.x); fma2(acc[r][1], pp, h1.y);
                pp = pk2(pv.z); fma2(acc[r][0], pp, h2.x); fma2(acc[r][1], pp, h2.y);
                pp = pk2(pv.w); fma2(acc[r][0], pp, h3.x); fma2(acc[r][1], pp, h3.y);
            }
        }
        __syncthreads();
    }

    if (t < RT) g_Zp[sp * N_ + rb * RT + t] = z_s[t];
#pragma unroll
    for (int r = 0; r < 8; ++r) {
        int rg = rb * RT + ry + r;
        float lo0, lo1, hi0, hi1;
        asm("mov.b64 {%0, %1}, %2;" : "=f"(lo0), "=f"(lo1) : "l"(acc[r][0]));
        asm("mov.b64 {%0, %1}, %2;" : "=f"(hi0), "=f"(hi1) : "l"(acc[r][1]));
        *reinterpret_cast<float4*>(&g_hp[((size_t)sp * N_ + rg) * OF + tx * 4]) =
            make_float4(lo0, lo1, hi0, hi1);
    }
}

// ============================================================
// Kernel 5: invZ[i] = 1 / sum_splits Zp
// ============================================================
__global__ void k_invz() {
    int i = blockIdx.x * 1024 + threadIdx.x;
    float z = g_Zp[i] + g_Zp[N_ + i] + g_Zp[2 * N_ + i] + g_Zp[3 * N_ + i];
    g_invZ[i] = 1.0f / z;
}

// ============================================================
// Kernel 6: h_prime = (sum_splits hp_part) * invZ  -> d_out[0:N*OF]
// ============================================================
__global__ void k_merge(float* __restrict__ out) {
    size_t idx = (size_t)blockIdx.x * 1024 + threadIdx.x;
    int row = (int)(idx >> 7);
    float s = g_hp[idx]
            + g_hp[(size_t)1 * N_ * OF + idx]
            + g_hp[(size_t)2 * N_ * OF + idx]
            + g_hp[(size_t)3 * N_ * OF + idx];
    out[idx] = s * g_invZ[row];
}

// ============================================================
// Kernel 7: attention[i][j] = adj ? exp(lrelu(src+tgt)-M)*invZ : 0
//           (recompute; identical fp expressions as k_main)
// ============================================================
__global__ __launch_bounds__(256) void k_attn(const int* __restrict__ adj, float* __restrict__ out) {
    const int row = blockIdx.x;
    const int t = threadIdx.x;
    const float sv = g_src[row];
    float e0 = sv + g_Tmax;
    const float m  = (e0 >= 0.f) ? e0 : SLOPE * e0;
    const float iz = g_invZ[row];
    const int4* arow = reinterpret_cast<const int4*>(adj + (size_t)row * N_);
    float4* orow = reinterpret_cast<float4*>(out + (size_t)row * N_);
#pragma unroll
    for (int it = 0; it < N_ / 4 / 256; ++it) {
        int j4 = it * 256 + t;
        int4 av = arow[j4];
        float4 tv = reinterpret_cast<const float4*>(g_tgt)[j4];
        float4 o;
        float e, lr;
        e = sv + tv.x; lr = (e >= 0.f) ? e : SLOPE * e; o.x = (av.x > 0) ? __expf(lr - m) * iz : 0.f;
        e = sv + tv.y; lr = (e >= 0.f) ? e : SLOPE * e; o.y = (av.y > 0) ? __expf(lr - m) * iz : 0.f;
        e = sv + tv.z; lr = (e >= 0.f) ? e : SLOPE * e; o.z = (av.z > 0) ? __expf(lr - m) * iz : 0.f;
        e = sv + tv.w; lr = (e >= 0.f) ? e : SLOPE * e; o.w = (av.w > 0) ? __expf(lr - m) * iz : 0.f;
        orow[j4] = o;
    }
}

// ============================================================
extern "C" void kernel_launch(void* const* d_in, const int* in_sizes, int n_in,
                              void* d_out, int out_size) {
    const float* h   = (const float*)d_in[0];
    const int*   adj = (const int*)d_in[1];
    const float* W   = (const float*)d_in[2];
    const float* a   = (const float*)d_in[3];
    float* out = (float*)d_out;

    k_ht<<<N_ / 64, 256>>>(h, W);
    k_srctgt<<<N_ / 8, 256>>>(a);
    k_tmax<<<1, 1024>>>();
    k_main<<<(N_ / RT) * NSPLIT, 256>>>(adj);
    k_invz<<<N_ / 1024, 1024>>>();
    k_merge<<<(N_ * OF) / 1024, 1024>>>(out);
    k_attn<<<N_, 256>>>(adj, out + (size_t)N_ * OF);
}

// round 8
// speedup vs baseline: 1.8249x; 1.8249x over previous
#include <cuda_runtime.h>
#include <cstdint>
#include <cstddef>

// GraphAttentionLayer: N=12288, IN_F=256, OUT_F=128
// out = [h_prime (N*128 f32) | attention (N*N f32)]

constexpr int N_  = 12288;
constexpr int INF = 256;
constexpr int OF  = 128;
constexpr float SLOPE = 0.2f;

// ---- k_main tiling (warp-level bf16 mma.sync) ----
constexpr int RT = 128;             // rows per CTA (MMA M)
constexpr int KT = 32;              // j per tile
constexpr int NSPLIT = 6;           // j-dimension split for load balance
constexpr int JSEG = N_ / NSPLIT;   // 2048
constexpr int NTILE = JSEG / KT;    // 64

// smem stage layout: rows padded to 80B (32 bf16 = 64B used) for
// conflict-free ldmatrix (stride 80B hits distinct bank quads).
constexpr int ROWB = 80;
constexpr int AHI_OFF = 0;                    // p hi   [128 r x 32 bf16]
constexpr int ALO_OFF = 128 * ROWB;           // 10240
constexpr int BHI_OFF = 2 * 128 * ROWB;       // htT hi [128 c x 32 bf16]
constexpr int BLO_OFF = 3 * 128 * ROWB;
constexpr int STAGE_BYTES = 4 * 128 * ROWB;   // 40960
constexpr int DYN_SMEM = 2 * STAGE_BYTES;     // 81920

// ---- scratch (static device arrays; no allocation allowed) ----
__device__ float g_ht[(size_t)N_ * OF];              // h @ W               6 MB
__device__ uint16_t g_htT_hi[(size_t)OF * N_];       // h_t^T bf16 hi       3 MB
__device__ uint16_t g_htT_lo[(size_t)OF * N_];       // h_t^T bf16 lo       3 MB
__device__ float g_src[N_];
__device__ float g_tgt[N_];
__device__ float g_Tmax;
__device__ float g_Zp[NSPLIT * N_];                  // partial Z per split
__device__ float g_hp[(size_t)NSPLIT * N_ * OF];     // partial h_prime    37.7 MB
__device__ float g_invZ[N_];

// ============================================================
// helpers
// ============================================================
__device__ __forceinline__ uint32_t cvta_smem(const void* p) {
    uint32_t a;
    asm("{ .reg .u64 t; cvta.to.shared.u64 t, %1; cvt.u32.u64 %0, t; }" : "=r"(a) : "l"(p));
    return a;
}

// ldmatrix 4x (8x8 b16) from shared
__device__ __forceinline__ void ldsm_x4(uint32_t r[4], uint32_t addr) {
    asm volatile("ldmatrix.sync.aligned.m8n8.x4.shared.b16 {%0,%1,%2,%3}, [%4];"
                 : "=r"(r[0]), "=r"(r[1]), "=r"(r[2]), "=r"(r[3]) : "r"(addr));
}

// mma m16n8k16 bf16 -> f32, D += A*B
__device__ __forceinline__ void mma16816(float c[4], const uint32_t a[4], const uint32_t b[2]) {
    asm volatile(
        "mma.sync.aligned.m16n8k16.row.col.f32.bf16.bf16.f32 "
        "{%0,%1,%2,%3}, {%4,%5,%6,%7}, {%8,%9}, {%0,%1,%2,%3};"
        : "+f"(c[0]), "+f"(c[1]), "+f"(c[2]), "+f"(c[3])
        : "r"(a[0]), "r"(a[1]), "r"(a[2]), "r"(a[3]), "r"(b[0]), "r"(b[1]));
}

// bf16 split: h2 = packed bf16x2 of (a,b) (a in low half), residuals in l2
__device__ __forceinline__ void bf16_split2(float a, float b, uint32_t& h2, uint32_t& l2) {
    asm("cvt.rn.bf16x2.f32 %0, %1, %2;" : "=r"(h2) : "f"(b), "f"(a));
    float ha = __uint_as_float(h2 << 16);
    float hb = __uint_as_float(h2 & 0xffff0000u);
    float la = a - ha;
    float lb = b - hb;
    asm("cvt.rn.bf16x2.f32 %0, %1, %2;" : "=r"(l2) : "f"(lb), "f"(la));
}

// ============================================================
// Kernel 1: h_t = h @ W   (M=12288, K=256, N=128)
// ============================================================
__global__ __launch_bounds__(256) void k_ht(const float* __restrict__ h, const float* __restrict__ W) {
    __shared__ float As[64 * 32];
    __shared__ float Bs[32 * 128];
    const int t = threadIdx.x, tx = t & 31, ty = t >> 5;
    const int r0 = blockIdx.x * 64;
    float4 acc[8];
#pragma unroll
    for (int r = 0; r < 8; ++r) acc[r] = make_float4(0.f, 0.f, 0.f, 0.f);

    for (int k0 = 0; k0 < INF; k0 += 32) {
#pragma unroll
        for (int k = 0; k < 2; ++k) {
            int id = t + k * 256;
            int row = id >> 3, c4 = id & 7;
            reinterpret_cast<float4*>(As)[id] =
                *reinterpret_cast<const float4*>(h + (size_t)(r0 + row) * INF + k0 + c4 * 4);
        }
#pragma unroll
        for (int k = 0; k < 4; ++k) {
            int id = t + k * 256;
            int row = id >> 5, c4 = id & 31;
            reinterpret_cast<float4*>(Bs)[id] =
                *reinterpret_cast<const float4*>(W + (size_t)(k0 + row) * OF + c4 * 4);
        }
        __syncthreads();
#pragma unroll
        for (int kk = 0; kk < 32; ++kk) {
            float4 b = reinterpret_cast<const float4*>(Bs)[kk * 32 + tx];
#pragma unroll
            for (int r = 0; r < 8; ++r) {
                float a = As[(ty * 8 + r) * 32 + kk];
                acc[r].x = fmaf(a, b.x, acc[r].x);
                acc[r].y = fmaf(a, b.y, acc[r].y);
                acc[r].z = fmaf(a, b.z, acc[r].z);
                acc[r].w = fmaf(a, b.w, acc[r].w);
            }
        }
        __syncthreads();
    }
#pragma unroll
    for (int r = 0; r < 8; ++r)
        *reinterpret_cast<float4*>(&g_ht[(size_t)(r0 + ty * 8 + r) * OF + tx * 4]) = acc[r];
}

// ============================================================
// Kernel 1b: h_t^T bf16 hi/lo split   g_htT_*[c][j]
// ============================================================
__global__ __launch_bounds__(256) void k_htT() {
    __shared__ float ts[32 * 129];
    const int jb = blockIdx.x;          // 384 blocks of 32 j each
    const int t = threadIdx.x;
#pragma unroll
    for (int k = 0; k < 4; ++k) {
        int id = t + k * 256;           // 1024 float4 loads
        int jl = id >> 5, c4 = id & 31;
        float4 v = *reinterpret_cast<const float4*>(
            g_ht + (size_t)(jb * 32 + jl) * OF + c4 * 4);
        ts[jl * 129 + c4 * 4 + 0] = v.x;
        ts[jl * 129 + c4 * 4 + 1] = v.y;
        ts[jl * 129 + c4 * 4 + 2] = v.z;
        ts[jl * 129 + c4 * 4 + 3] = v.w;
    }
    __syncthreads();
    const int c = t >> 1, jh = t & 1;   // 128 c rows, 16 j per thread
    uint32_t hw[8], lw[8];
#pragma unroll
    for (int i = 0; i < 8; ++i) {
        float a = ts[(jh * 16 + 2 * i + 0) * 129 + c];
        float b = ts[(jh * 16 + 2 * i + 1) * 129 + c];
        bf16_split2(a, b, hw[i], lw[i]);
    }
    size_t eo = (size_t)c * N_ + jb * 32 + jh * 16;
    *reinterpret_cast<uint4*>(reinterpret_cast<char*>(g_htT_hi) + eo * 2) =
        make_uint4(hw[0], hw[1], hw[2], hw[3]);
    *reinterpret_cast<uint4*>(reinterpret_cast<char*>(g_htT_hi) + eo * 2 + 16) =
        make_uint4(hw[4], hw[5], hw[6], hw[7]);
    *reinterpret_cast<uint4*>(reinterpret_cast<char*>(g_htT_lo) + eo * 2) =
        make_uint4(lw[0], lw[1], lw[2], lw[3]);
    *reinterpret_cast<uint4*>(reinterpret_cast<char*>(g_htT_lo) + eo * 2 + 16) =
        make_uint4(lw[4], lw[5], lw[6], lw[7]);
}

// ============================================================
// Kernel 2: src = h_t @ a[:128], tgt = h_t @ a[128:]
// ============================================================
__global__ __launch_bounds__(256) void k_srctgt(const float* __restrict__ a) {
    const int t = threadIdx.x;
    const int lane = t & 31;
    const int row = blockIdx.x * 8 + (t >> 5);
    float4 hv = *reinterpret_cast<const float4*>(g_ht + (size_t)row * OF + lane * 4);
    float4 a1 = *reinterpret_cast<const float4*>(a + lane * 4);
    float4 a2 = *reinterpret_cast<const float4*>(a + OF + lane * 4);
    float s1 = hv.x * a1.x + hv.y * a1.y + hv.z * a1.z + hv.w * a1.w;
    float s2 = hv.x * a2.x + hv.y * a2.y + hv.z * a2.z + hv.w * a2.w;
#pragma unroll
    for (int off = 16; off > 0; off >>= 1) {
        s1 += __shfl_xor_sync(0xffffffffu, s1, off);
        s2 += __shfl_xor_sync(0xffffffffu, s2, off);
    }
    if (lane == 0) { g_src[row] = s1; g_tgt[row] = s2; }
}

// ============================================================
// Kernel 3: Tmax = max(tgt)
// ============================================================
__global__ void k_tmax() {
    __shared__ float red[1024];
    const int t = threadIdx.x;
    float m = -3.402823466e38f;
    for (int i = t; i < N_; i += 1024) m = fmaxf(m, g_tgt[i]);
    red[t] = m;
    __syncthreads();
    for (int s = 512; s > 0; s >>= 1) {
        if (t < s) red[t] = fmaxf(red[t], red[t + s]);
        __syncthreads();
    }
    if (t == 0) g_Tmax = red[0];
}

// ============================================================
// Kernel 4 (main): per (128-row block, 1/NSPLIT of columns):
//   p_ij = adj ? exp(lrelu(src_i+tgt_j) - M_i) : 0
//   Zp[i]  = sum_j p_ij            (register accumulation)
//   hp[i]  = sum_j p_ij * h_t[j]   (bf16-split mma.sync, fp32 accum)
// Split x = hi + lo (bf16); D += Ahi*Bhi + Ahi*Blo + Alo*Bhi.
// 8 warps in 4x2 grid: warp tile 32 rows x 64 cols.
// Double-buffered smem stage, one __syncthreads per tile, adj
// prefetched in registers across the barrier.
// ============================================================
__global__ __launch_bounds__(256, 2) void k_main(const int* __restrict__ adj) {
    extern __shared__ char smem[];
    const uint32_t sbase = cvta_smem(smem);

    const int t = threadIdx.x;
    const int lane = t & 31, wid = t >> 5;
    const int rb = blockIdx.x / NSPLIT;     // row block 0..95
    const int sp = blockIdx.x % NSPLIT;     // j split 0..5
    const int jbase = sp * JSEG;

    // phase-A identity: 2 threads per row, 16 j each
    const int row = t >> 1, half = t & 1;
    const int grow = rb * RT + row;
    const float srcv = g_src[grow];
    float e0 = srcv + g_Tmax;
    const float mv = fmaxf(e0, SLOPE * e0);
    float zacc = 0.f;
    const uint32_t a_st = (uint32_t)row * ROWB + half * 32;

    // B staging: 2 x 16B chunks per thread (512 chunks of [128 c x 64B rows])
    const int bc0 = (2 * t) >> 2, bq0 = (2 * t) & 3;
    const int bc1 = (2 * t + 1) >> 2, bq1 = (2 * t + 1) & 3;

    // ldmatrix per-lane address offsets
    const int wrow = wid >> 1, wcol = wid & 1;          // 4x2 warp grid
    const uint32_t a_lds = ((lane & 7) + ((lane >> 3) & 1) * 8) * ROWB + ((lane >> 4) & 1) * 16;
    const uint32_t b_lds = ((lane & 7) + ((lane >> 4) & 1) * 8) * ROWB + ((lane >> 3) & 1) * 16;

    float acc[2][8][4];
#pragma unroll
    for (int m = 0; m < 2; ++m)
#pragma unroll
        for (int n = 0; n < 8; ++n)
#pragma unroll
            for (int k = 0; k < 4; ++k) acc[m][n][k] = 0.f;

    // prefetch adj for tile 0
    int4 padj[4];
    {
        const int4* ap = reinterpret_cast<const int4*>(adj + (size_t)grow * N_ + jbase + half * 16);
#pragma unroll
        for (int i = 0; i < 4; ++i) padj[i] = ap[i];
    }

    for (int tt = 0; tt < NTILE; ++tt) {
        const uint32_t stage = sbase + (uint32_t)(tt & 1) * STAGE_BYTES;
        const int j0 = jbase + tt * KT;

        // ---- phase A: p -> A_hi/A_lo bf16 ----
        {
            const float4* tp = reinterpret_cast<const float4*>(g_tgt + j0 + half * 16);
            float pv[16];
#pragma unroll
            for (int c4 = 0; c4 < 4; ++c4) {
                float4 tv = tp[c4];
                const int* av = reinterpret_cast<const int*>(&padj[c4]);
                float tvv[4] = {tv.x, tv.y, tv.z, tv.w};
#pragma unroll
                for (int u = 0; u < 4; ++u) {
                    float e  = srcv + tvv[u];
                    float lr = fmaxf(e, SLOPE * e);
                    float ex = __expf(lr - mv);
                    float p  = (av[u] > 0) ? ex : 0.f;
                    pv[c4 * 4 + u] = p;
                    zacc += p;
                }
            }
            uint32_t hw[8], lw[8];
#pragma unroll
            for (int i = 0; i < 8; ++i)
                bf16_split2(pv[2 * i], pv[2 * i + 1], hw[i], lw[i]);
            uint32_t dst = stage + AHI_OFF + a_st;
            asm volatile("st.shared.v4.b32 [%0], {%1,%2,%3,%4};" ::
                         "r"(dst), "r"(hw[0]), "r"(hw[1]), "r"(hw[2]), "r"(hw[3]));
            asm volatile("st.shared.v4.b32 [%0], {%1,%2,%3,%4};" ::
                         "r"(dst + 16), "r"(hw[4]), "r"(hw[5]), "r"(hw[6]), "r"(hw[7]));
            dst = stage + ALO_OFF + a_st;
            asm volatile("st.shared.v4.b32 [%0], {%1,%2,%3,%4};" ::
                         "r"(dst), "r"(lw[0]), "r"(lw[1]), "r"(lw[2]), "r"(lw[3]));
            asm volatile("st.shared.v4.b32 [%0], {%1,%2,%3,%4};" ::
                         "r"(dst + 16), "r"(lw[4]), "r"(lw[5]), "r"(lw[6]), "r"(lw[7]));
        }

        // ---- stage B: htT hi/lo (global, L2-hot) -> smem ----
        {
            size_t e0g = (size_t)bc0 * N_ + j0 + bq0 * 8;
            size_t e1g = (size_t)bc1 * N_ + j0 + bq1 * 8;
            uint4 vh0 = *reinterpret_cast<const uint4*>(reinterpret_cast<const char*>(g_htT_hi) + e0g * 2);
            uint4 vh1 = *reinterpret_cast<const uint4*>(reinterpret_cast<const char*>(g_htT_hi) + e1g * 2);
            uint4 vl0 = *reinterpret_cast<const uint4*>(reinterpret_cast<const char*>(g_htT_lo) + e0g * 2);
            uint4 vl1 = *reinterpret_cast<const uint4*>(reinterpret_cast<const char*>(g_htT_lo) + e1g * 2);
            uint32_t d0 = stage + BHI_OFF + bc0 * ROWB + bq0 * 16;
            uint32_t d1 = stage + BHI_OFF + bc1 * ROWB + bq1 * 16;
            asm volatile("st.shared.v4.b32 [%0], {%1,%2,%3,%4};" ::
                         "r"(d0), "r"(vh0.x), "r"(vh0.y), "r"(vh0.z), "r"(vh0.w));
            asm volatile("st.shared.v4.b32 [%0], {%1,%2,%3,%4};" ::
                         "r"(d1), "r"(vh1.x), "r"(vh1.y), "r"(vh1.z), "r"(vh1.w));
            asm volatile("st.shared.v4.b32 [%0], {%1,%2,%3,%4};" ::
                         "r"(d0 + (BLO_OFF - BHI_OFF)), "r"(vl0.x), "r"(vl0.y), "r"(vl0.z), "r"(vl0.w));
            asm volatile("st.shared.v4.b32 [%0], {%1,%2,%3,%4};" ::
                         "r"(d1 + (BLO_OFF - BHI_OFF)), "r"(vl1.x), "r"(vl1.y), "r"(vl1.z), "r"(vl1.w));
        }

        __syncthreads();

        // ---- prefetch adj for next tile (no hazard: regs only) ----
        if (tt + 1 < NTILE) {
            const int4* ap = reinterpret_cast<const int4*>(
                adj + (size_t)grow * N_ + jbase + (tt + 1) * KT + half * 16);
#pragma unroll
            for (int i = 0; i < 4; ++i) padj[i] = ap[i];
        }

        // ---- phase B: mma (3 split passes share the f32 accumulators) ----
#pragma unroll
        for (int kk = 0; kk < 2; ++kk) {
            uint32_t ah0[4], ah1[4], al0[4], al1[4];
            uint32_t ab = stage + AHI_OFF + (uint32_t)(wrow * 32) * ROWB + kk * 32 + a_lds;
            ldsm_x4(ah0, ab);
            ldsm_x4(ah1, ab + 16 * ROWB);
            uint32_t alb = ab + (ALO_OFF - AHI_OFF);
            ldsm_x4(al0, alb);
            ldsm_x4(al1, alb + 16 * ROWB);
#pragma unroll
            for (int nc = 0; nc < 4; ++nc) {
                uint32_t bh[4], bl[4];
                uint32_t bb = stage + BHI_OFF + (uint32_t)(wcol * 64 + nc * 16) * ROWB + kk * 32 + b_lds;
                ldsm_x4(bh, bb);
                ldsm_x4(bl, bb + (BLO_OFF - BHI_OFF));
                const int n0 = nc * 2, n1 = nc * 2 + 1;
                mma16816(acc[0][n0], ah0, bh);
                mma16816(acc[1][n0], ah1, bh);
                mma16816(acc[0][n1], ah0, bh + 2);
                mma16816(acc[1][n1], ah1, bh + 2);
                mma16816(acc[0][n0], ah0, bl);
                mma16816(acc[1][n0], ah1, bl);
                mma16816(acc[0][n1], ah0, bl + 2);
                mma16816(acc[1][n1], ah1, bl + 2);
                mma16816(acc[0][n0], al0, bh);
                mma16816(acc[1][n0], al1, bh);
                mma16816(acc[0][n1], al0, bh + 2);
                mma16816(acc[1][n1], al1, bh + 2);
            }
        }
    }

    // Zp: combine the two half-row threads
    float zsum = zacc + __shfl_xor_sync(0xffffffffu, zacc, 1);
    if (half == 0) g_Zp[sp * N_ + grow] = zsum;

    // epilogue: fragment -> g_hp partial
    const int er0 = rb * RT + wrow * 32 + (lane >> 2);
    const int ec0 = wcol * 64 + 2 * (lane & 3);
#pragma unroll
    for (int m = 0; m < 2; ++m) {
#pragma unroll
        for (int n = 0; n < 8; ++n) {
            size_t base = ((size_t)sp * N_ + er0 + m * 16) * OF + ec0 + n * 8;
            *reinterpret_cast<float2*>(g_hp + base) = make_float2(acc[m][n][0], acc[m][n][1]);
            *reinterpret_cast<float2*>(g_hp + base + (size_t)8 * OF) = make_float2(acc[m][n][2], acc[m][n][3]);
        }
    }
}

// ============================================================
// Kernel 5: invZ[i] = 1 / sum_splits Zp
// ============================================================
__global__ void k_invz() {
    int i = blockIdx.x * 1024 + threadIdx.x;
    float z = 0.f;
#pragma unroll
    for (int s = 0; s < NSPLIT; ++s) z += g_Zp[s * N_ + i];
    g_invZ[i] = 1.0f / z;
}

// ============================================================
// Kernel 6: h_prime = (sum_splits hp_part) * invZ  -> d_out[0:N*OF]
// ============================================================
__global__ void k_merge(float* __restrict__ out) {
    size_t idx = (size_t)blockIdx.x * 1024 + threadIdx.x;
    int row = (int)(idx >> 7);
    float s = 0.f;
#pragma unroll
    for (int p = 0; p < NSPLIT; ++p) s += g_hp[(size_t)p * N_ * OF + idx];
    out[idx] = s * g_invZ[row];
}

// ============================================================
// Kernel 7: attention[i][j] = adj ? exp(lrelu(src+tgt)-M)*invZ : 0
// ============================================================
__global__ __launch_bounds__(256) void k_attn(const int* __restrict__ adj, float* __restrict__ out) {
    const int row = blockIdx.x;
    const int t = threadIdx.x;
    const float sv = g_src[row];
    float e0 = sv + g_Tmax;
    const float m  = fmaxf(e0, SLOPE * e0);
    const float iz = g_invZ[row];
    const int4* arow = reinterpret_cast<const int4*>(adj + (size_t)row * N_);
    float4* orow = reinterpret_cast<float4*>(out + (size_t)row * N_);
#pragma unroll
    for (int it = 0; it < N_ / 4 / 256; ++it) {
        int j4 = it * 256 + t;
        int4 av = arow[j4];
        float4 tv = reinterpret_cast<const float4*>(g_tgt)[j4];
        float4 o;
        float e, lr;
        e = sv + tv.x; lr = fmaxf(e, SLOPE * e); o.x = (av.x > 0) ? __expf(lr - m) * iz : 0.f;
        e = sv + tv.y; lr = fmaxf(e, SLOPE * e); o.y = (av.y > 0) ? __expf(lr - m) * iz : 0.f;
        e = sv + tv.z; lr = fmaxf(e, SLOPE * e); o.z = (av.z > 0) ? __expf(lr - m) * iz : 0.f;
        e = sv + tv.w; lr = fmaxf(e, SLOPE * e); o.w = (av.w > 0) ? __expf(lr - m) * iz : 0.f;
        orow[j4] = o;
    }
}

// ============================================================
extern "C" void kernel_launch(void* const* d_in, const int* in_sizes, int n_in,
                              void* d_out, int out_size) {
    const float* h   = (const float*)d_in[0];
    const int*   adj = (const int*)d_in[1];
    const float* W   = (const float*)d_in[2];
    const float* a   = (const float*)d_in[3];
    float* out = (float*)d_out;

    cudaFuncSetAttribute(k_main, cudaFuncAttributeMaxDynamicSharedMemorySize, DYN_SMEM);

    k_ht<<<N_ / 64, 256>>>(h, W);
    k_srctgt<<<N_ / 8, 256>>>(a);
    k_tmax<<<1, 1024>>>();
    k_htT<<<N_ / 32, 256>>>();
    k_main<<<(N_ / RT) * NSPLIT, 256, DYN_SMEM>>>(adj);
    k_invz<<<N_ / 1024, 1024>>>();
    k_merge<<<(N_ * OF) / 1024, 1024>>>(out);
    k_attn<<<N_, 256>>>(adj, out + (size_t)N_ * OF);
}

// round 9
// speedup vs baseline: 1.8610x; 1.0198x over previous
#include <cuda_runtime.h>
#include <cstdint>
#include <cstddef>

// GraphAttentionLayer: N=12288, IN_F=256, OUT_F=128
// out = [h_prime (N*128 f32) | attention (N*N f32)]

constexpr int N_  = 12288;
constexpr int INF = 256;
constexpr int OF  = 128;
constexpr float SLOPE = 0.2f;

// ---- k_main tiling (warp-level bf16 mma.sync) ----
constexpr int RT = 128;             // rows per CTA (MMA M)
constexpr int KT = 32;              // j per tile
constexpr int NSPLIT = 6;           // j-dimension split for load balance
constexpr int JSEG = N_ / NSPLIT;   // 2048
constexpr int NTILE = JSEG / KT;    // 64

// smem stage layout: rows padded to 80B (32 bf16 = 64B used) for
// conflict-free ldmatrix (stride 80B hits distinct bank quads).
constexpr int ROWB = 80;
constexpr int AHI_OFF = 0;                    // p hi   [128 r x 32 bf16]
constexpr int ALO_OFF = 128 * ROWB;           // 10240
constexpr int BHI_OFF = 2 * 128 * ROWB;       // htT hi [128 c x 32 bf16]
constexpr int BLO_OFF = 3 * 128 * ROWB;
constexpr int STAGE_BYTES = 4 * 128 * ROWB;   // 40960
constexpr int DYN_SMEM = 2 * STAGE_BYTES;     // 81920

// ---- scratch (static device arrays; no allocation allowed) ----
__device__ float g_ht[(size_t)N_ * OF];              // h @ W               6 MB
__device__ uint16_t g_htT_hi[(size_t)OF * N_];       // h_t^T bf16 hi       3 MB
__device__ uint16_t g_htT_lo[(size_t)OF * N_];       // h_t^T bf16 lo       3 MB
__device__ float g_src[N_];
__device__ float g_tgt[N_];
__device__ float g_Tmax;
__device__ float2 g_EF[N_];                          // (E_j, F_j) tables  96 KB
__device__ uint32_t g_mask[(size_t)N_ * N_ / 32];    // adj bitmask        18.9 MB
__device__ float g_Zp[NSPLIT * N_];                  // partial Z per split
__device__ float g_hp[(size_t)NSPLIT * N_ * OF];     // partial h_prime    37.7 MB
__device__ float g_invZ[N_];

// ============================================================
// helpers
// ============================================================
__device__ __forceinline__ uint32_t cvta_smem(const void* p) {
    uint32_t a;
    asm("{ .reg .u64 t; cvta.to.shared.u64 t, %1; cvt.u32.u64 %0, t; }" : "=r"(a) : "l"(p));
    return a;
}

// ldmatrix 4x (8x8 b16) from shared
__device__ __forceinline__ void ldsm_x4(uint32_t r[4], uint32_t addr) {
    asm volatile("ldmatrix.sync.aligned.m8n8.x4.shared.b16 {%0,%1,%2,%3}, [%4];"
                 : "=r"(r[0]), "=r"(r[1]), "=r"(r[2]), "=r"(r[3]) : "r"(addr));
}

// mma m16n8k16 bf16 -> f32, D += A*B
__device__ __forceinline__ void mma16816(float c[4], const uint32_t a[4], const uint32_t b[2]) {
    asm volatile(
        "mma.sync.aligned.m16n8k16.row.col.f32.bf16.bf16.f32 "
        "{%0,%1,%2,%3}, {%4,%5,%6,%7}, {%8,%9}, {%0,%1,%2,%3};"
        : "+f"(c[0]), "+f"(c[1]), "+f"(c[2]), "+f"(c[3])
        : "r"(a[0]), "r"(a[1]), "r"(a[2]), "r"(a[3]), "r"(b[0]), "r"(b[1]));
}

// bf16 split: h2 = packed bf16x2 of (a,b) (a in low half), residuals in l2
__device__ __forceinline__ void bf16_split2(float a, float b, uint32_t& h2, uint32_t& l2) {
    asm("cvt.rn.bf16x2.f32 %0, %1, %2;" : "=r"(h2) : "f"(b), "f"(a));
    float ha = __uint_as_float(h2 << 16);
    float hb = __uint_as_float(h2 & 0xffff0000u);
    float la = a - ha;
    float lb = b - hb;
    asm("cvt.rn.bf16x2.f32 %0, %1, %2;" : "=r"(l2) : "f"(lb), "f"(la));
}

// ============================================================
// Kernel 1: h_t = h @ W   (M=12288, K=256, N=128)
// ============================================================
__global__ __launch_bounds__(256) void k_ht(const float* __restrict__ h, const float* __restrict__ W) {
    __shared__ float As[64 * 32];
    __shared__ float Bs[32 * 128];
    const int t = threadIdx.x, tx = t & 31, ty = t >> 5;
    const int r0 = blockIdx.x * 64;
    float4 acc[8];
#pragma unroll
    for (int r = 0; r < 8; ++r) acc[r] = make_float4(0.f, 0.f, 0.f, 0.f);

    for (int k0 = 0; k0 < INF; k0 += 32) {
#pragma unroll
        for (int k = 0; k < 2; ++k) {
            int id = t + k * 256;
            int row = id >> 3, c4 = id & 7;
            reinterpret_cast<float4*>(As)[id] =
                *reinterpret_cast<const float4*>(h + (size_t)(r0 + row) * INF + k0 + c4 * 4);
        }
#pragma unroll
        for (int k = 0; k < 4; ++k) {
            int id = t + k * 256;
            int row = id >> 5, c4 = id & 31;
            reinterpret_cast<float4*>(Bs)[id] =
                *reinterpret_cast<const float4*>(W + (size_t)(k0 + row) * OF + c4 * 4);
        }
        __syncthreads();
#pragma unroll
        for (int kk = 0; kk < 32; ++kk) {
            float4 b = reinterpret_cast<const float4*>(Bs)[kk * 32 + tx];
#pragma unroll
            for (int r = 0; r < 8; ++r) {
                float a = As[(ty * 8 + r) * 32 + kk];
                acc[r].x = fmaf(a, b.x, acc[r].x);
                acc[r].y = fmaf(a, b.y, acc[r].y);
                acc[r].z = fmaf(a, b.z, acc[r].z);
                acc[r].w = fmaf(a, b.w, acc[r].w);
            }
        }
        __syncthreads();
    }
#pragma unroll
    for (int r = 0; r < 8; ++r)
        *reinterpret_cast<float4*>(&g_ht[(size_t)(r0 + ty * 8 + r) * OF + tx * 4]) = acc[r];
}

// ============================================================
// Kernel 1b: h_t^T bf16 hi/lo split   g_htT_*[c][j]
// ============================================================
__global__ __launch_bounds__(256) void k_htT() {
    __shared__ float ts[32 * 129];
    const int jb = blockIdx.x;          // 384 blocks of 32 j each
    const int t = threadIdx.x;
#pragma unroll
    for (int k = 0; k < 4; ++k) {
        int id = t + k * 256;           // 1024 float4 loads
        int jl = id >> 5, c4 = id & 31;
        float4 v = *reinterpret_cast<const float4*>(
            g_ht + (size_t)(jb * 32 + jl) * OF + c4 * 4);
        ts[jl * 129 + c4 * 4 + 0] = v.x;
        ts[jl * 129 + c4 * 4 + 1] = v.y;
        ts[jl * 129 + c4 * 4 + 2] = v.z;
        ts[jl * 129 + c4 * 4 + 3] = v.w;
    }
    __syncthreads();
    const int c = t >> 1, jh = t & 1;   // 128 c rows, 16 j per thread
    uint32_t hw[8], lw[8];
#pragma unroll
    for (int i = 0; i < 8; ++i) {
        float a = ts[(jh * 16 + 2 * i + 0) * 129 + c];
        float b = ts[(jh * 16 + 2 * i + 1) * 129 + c];
        bf16_split2(a, b, hw[i], lw[i]);
    }
    size_t eo = (size_t)c * N_ + jb * 32 + jh * 16;
    *reinterpret_cast<uint4*>(reinterpret_cast<char*>(g_htT_hi) + eo * 2) =
        make_uint4(hw[0], hw[1], hw[2], hw[3]);
    *reinterpret_cast<uint4*>(reinterpret_cast<char*>(g_htT_hi) + eo * 2 + 16) =
        make_uint4(hw[4], hw[5], hw[6], hw[7]);
    *reinterpret_cast<uint4*>(reinterpret_cast<char*>(g_htT_lo) + eo * 2) =
        make_uint4(lw[0], lw[1], lw[2], lw[3]);
    *reinterpret_cast<uint4*>(reinterpret_cast<char*>(g_htT_lo) + eo * 2 + 16) =
        make_uint4(lw[4], lw[5], lw[6], lw[7]);
}

// ============================================================
// Kernel 2: src = h_t @ a[:128], tgt = h_t @ a[128:]
// ============================================================
__global__ __launch_bounds__(256) void k_srctgt(const float* __restrict__ a) {
    const int t = threadIdx.x;
    const int lane = t & 31;
    const int row = blockIdx.x * 8 + (t >> 5);
    float4 hv = *reinterpret_cast<const float4*>(g_ht + (size_t)row * OF + lane * 4);
    float4 a1 = *reinterpret_cast<const float4*>(a + lane * 4);
    float4 a2 = *reinterpret_cast<const float4*>(a + OF + lane * 4);
    float s1 = hv.x * a1.x + hv.y * a1.y + hv.z * a1.z + hv.w * a1.w;
    float s2 = hv.x * a2.x + hv.y * a2.y + hv.z * a2.z + hv.w * a2.w;
#pragma unroll
    for (int off = 16; off > 0; off >>= 1) {
        s1 += __shfl_xor_sync(0xffffffffu, s1, off);
        s2 += __shfl_xor_sync(0xffffffffu, s2, off);
    }
    if (lane == 0) { g_src[row] = s1; g_tgt[row] = s2; }
}

// ============================================================
// Kernel 3: Tmax = max(tgt)
// ============================================================
__global__ void k_tmax() {
    __shared__ float red[1024];
    const int t = threadIdx.x;
    float m = -3.402823466e38f;
    for (int i = t; i < N_; i += 1024) m = fmaxf(m, g_tgt[i]);
    red[t] = m;
    __syncthreads();
    for (int s = 512; s > 0; s >>= 1) {
        if (t < s) red[t] = fmaxf(red[t], red[t + s]);
        __syncthreads();
    }
    if (t == 0) g_Tmax = red[0];
}

// ============================================================
// Kernel 3b: E_j = exp(tgt_j - Tmax), F_j = exp(0.2*(tgt_j - Tmax))
// Separable-exp tables: exp(lrelu(s+t)-m) = (s+t>=0 ? C_i*E_j : D_i*F_j),
// branch test (s+t>=0) <=> (E_j >= G_i), G_i = exp(-(s_i+Tmax)).
// All factors <= 1 by construction of m_i = lrelu(s_i+Tmax).
// ============================================================
__global__ void k_ef() {
    int j = blockIdx.x * 256 + threadIdx.x;
    float tm = g_tgt[j] - g_Tmax;
    g_EF[j] = make_float2(__expf(tm), __expf(0.2f * tm));
}

// ============================================================
// Kernel 4 (main): per (128-row block, 1/NSPLIT of columns):
//   p_ij = adj ? (E_j>=G_i ? C_i*E_j : D_i*F_j) : 0   (no per-pair exp!)
//   Zp[i]  = sum_j p_ij            (register accumulation)
//   hp[i]  = sum_j p_ij * h_t[j]   (bf16-split mma.sync, fp32 accum)
//   g_mask = packed adj bits       (k_attn reads 19MB instead of 604MB)
// ============================================================
__global__ __launch_bounds__(256, 2) void k_main(const int* __restrict__ adj) {
    extern __shared__ char smem[];
    const uint32_t sbase = cvta_smem(smem);

    const int t = threadIdx.x;
    const int lane = t & 31, wid = t >> 5;
    const int rb = blockIdx.x / NSPLIT;     // row block 0..95
    const int sp = blockIdx.x % NSPLIT;     // j split 0..5
    const int jbase = sp * JSEG;

    // phase-A identity: 2 threads per row, 16 j each
    const int row = t >> 1, half = t & 1;
    const int grow = rb * RT + row;
    const float srcv = g_src[grow];
    float e0 = srcv + g_Tmax;
    const float mv = fmaxf(e0, SLOPE * e0);
    const float Cc = __expf(e0 - mv);
    const float Dc = __expf(SLOPE * e0 - mv);
    const float Gc = __expf(-e0);
    float zacc = 0.f;
    const uint32_t a_st = (uint32_t)row * ROWB + half * 32;

    // B staging: 2 x 16B chunks per thread (512 chunks of [128 c x 64B rows])
    const int bc0 = (2 * t) >> 2, bq0 = (2 * t) & 3;
    const int bc1 = (2 * t + 1) >> 2, bq1 = (2 * t + 1) & 3;

    // ldmatrix per-lane address offsets
    const int wrow = wid >> 1, wcol = wid & 1;          // 4x2 warp grid
    const uint32_t a_lds = ((lane & 7) + ((lane >> 3) & 1) * 8) * ROWB + ((lane >> 4) & 1) * 16;
    const uint32_t b_lds = ((lane & 7) + ((lane >> 4) & 1) * 8) * ROWB + ((lane >> 3) & 1) * 16;

    float acc[2][8][4];
#pragma unroll
    for (int m = 0; m < 2; ++m)
#pragma unroll
        for (int n = 0; n < 8; ++n)
#pragma unroll
            for (int k = 0; k < 4; ++k) acc[m][n][k] = 0.f;

    // prefetch adj for tile 0
    int4 padj[4];
    {
        const int4* ap = reinterpret_cast<const int4*>(adj + (size_t)grow * N_ + jbase + half * 16);
#pragma unroll
        for (int i = 0; i < 4; ++i) padj[i] = ap[i];
    }

    uint32_t mw[4];     // packed mask words, flushed every 4 tiles (half==0)

    for (int tt = 0; tt < NTILE; ++tt) {
        const uint32_t stage = sbase + (uint32_t)(tt & 1) * STAGE_BYTES;
        const int j0 = jbase + tt * KT;

        // ---- phase A: p -> A_hi/A_lo bf16 + mask bits ----
        {
            const float4* ef4 = reinterpret_cast<const float4*>(g_EF + j0 + half * 16);
            float pv[16];
            uint32_t mbits = 0;
#pragma unroll
            for (int c4 = 0; c4 < 4; ++c4) {
                const int* av = reinterpret_cast<const int*>(&padj[c4]);
                float4 efA = ef4[c4 * 2];       // (E,F) for j 4c4+0, 4c4+1
                float4 efB = ef4[c4 * 2 + 1];   // (E,F) for j 4c4+2, 4c4+3
                float Ev[4] = {efA.x, efA.z, efB.x, efB.z};
                float Fv[4] = {efA.y, efA.w, efB.y, efB.w};
#pragma unroll
                for (int u = 0; u < 4; ++u) {
                    bool pos = Ev[u] >= Gc;
                    float p  = (pos ? Cc : Dc) * (pos ? Ev[u] : Fv[u]);
                    bool on  = av[u] > 0;
                    p = on ? p : 0.f;
                    mbits |= (on ? 1u : 0u) << (c4 * 4 + u);
                    pv[c4 * 4 + u] = p;
                    zacc += p;
                }
            }
            // combine half0(low16)/half1(high16) into one mask word
            uint32_t other = __shfl_xor_sync(0xffffffffu, mbits, 1);
            mw[tt & 3] = half ? ((mbits << 16) | other) : (mbits | (other << 16));
            if ((tt & 3) == 3 && half == 0) {
                *reinterpret_cast<uint4*>(
                    g_mask + (size_t)grow * (N_ / 32) + (jbase >> 5) + (tt - 3)) =
                    make_uint4(mw[0], mw[1], mw[2], mw[3]);
            }

            uint32_t hw[8], lw[8];
#pragma unroll
            for (int i = 0; i < 8; ++i)
                bf16_split2(pv[2 * i], pv[2 * i + 1], hw[i], lw[i]);
            uint32_t dst = stage + AHI_OFF + a_st;
            asm volatile("st.shared.v4.b32 [%0], {%1,%2,%3,%4};" ::
                         "r"(dst), "r"(hw[0]), "r"(hw[1]), "r"(hw[2]), "r"(hw[3]));
            asm volatile("st.shared.v4.b32 [%0], {%1,%2,%3,%4};" ::
                         "r"(dst + 16), "r"(hw[4]), "r"(hw[5]), "r"(hw[6]), "r"(hw[7]));
            dst = stage + ALO_OFF + a_st;
            asm volatile("st.shared.v4.b32 [%0], {%1,%2,%3,%4};" ::
                         "r"(dst), "r"(lw[0]), "r"(lw[1]), "r"(lw[2]), "r"(lw[3]));
            asm volatile("st.shared.v4.b32 [%0], {%1,%2,%3,%4};" ::
                         "r"(dst + 16), "r"(lw[4]), "r"(lw[5]), "r"(lw[6]), "r"(lw[7]));
        }

        // ---- stage B: htT hi/lo (global, L2-hot) -> smem ----
        {
            size_t e0g = (size_t)bc0 * N_ + j0 + bq0 * 8;
            size_t e1g = (size_t)bc1 * N_ + j0 + bq1 * 8;
            uint4 vh0 = *reinterpret_cast<const uint4*>(reinterpret_cast<const char*>(g_htT_hi) + e0g * 2);
            uint4 vh1 = *reinterpret_cast<const uint4*>(reinterpret_cast<const char*>(g_htT_hi) + e1g * 2);
            uint4 vl0 = *reinterpret_cast<const uint4*>(reinterpret_cast<const char*>(g_htT_lo) + e0g * 2);
            uint4 vl1 = *reinterpret_cast<const uint4*>(reinterpret_cast<const char*>(g_htT_lo) + e1g * 2);
            uint32_t d0 = stage + BHI_OFF + bc0 * ROWB + bq0 * 16;
            uint32_t d1 = stage + BHI_OFF + bc1 * ROWB + bq1 * 16;
            asm volatile("st.shared.v4.b32 [%0], {%1,%2,%3,%4};" ::
                         "r"(d0), "r"(vh0.x), "r"(vh0.y), "r"(vh0.z), "r"(vh0.w));
            asm volatile("st.shared.v4.b32 [%0], {%1,%2,%3,%4};" ::
                         "r"(d1), "r"(vh1.x), "r"(vh1.y), "r"(vh1.z), "r"(vh1.w));
            asm volatile("st.shared.v4.b32 [%0], {%1,%2,%3,%4};" ::
                         "r"(d0 + (BLO_OFF - BHI_OFF)), "r"(vl0.x), "r"(vl0.y), "r"(vl0.z), "r"(vl0.w));
            asm volatile("st.shared.v4.b32 [%0], {%1,%2,%3,%4};" ::
                         "r"(d1 + (BLO_OFF - BHI_OFF)), "r"(vl1.x), "r"(vl1.y), "r"(vl1.z), "r"(vl1.w));
        }

        __syncthreads();

        // ---- prefetch adj for next tile (no hazard: regs only) ----
        if (tt + 1 < NTILE) {
            const int4* ap = reinterpret_cast<const int4*>(
                adj + (size_t)grow * N_ + jbase + (tt + 1) * KT + half * 16);
#pragma unroll
            for (int i = 0; i < 4; ++i) padj[i] = ap[i];
        }

        // ---- phase B: mma (3 split passes share the f32 accumulators) ----
#pragma unroll
        for (int kk = 0; kk < 2; ++kk) {
            uint32_t ah0[4], ah1[4], al0[4], al1[4];
            uint32_t ab = stage + AHI_OFF + (uint32_t)(wrow * 32) * ROWB + kk * 32 + a_lds;
            ldsm_x4(ah0, ab);
            ldsm_x4(ah1, ab + 16 * ROWB);
            uint32_t alb = ab + (ALO_OFF - AHI_OFF);
            ldsm_x4(al0, alb);
            ldsm_x4(al1, alb + 16 * ROWB);
#pragma unroll
            for (int nc = 0; nc < 4; ++nc) {
                uint32_t bh[4], bl[4];
                uint32_t bb = stage + BHI_OFF + (uint32_t)(wcol * 64 + nc * 16) * ROWB + kk * 32 + b_lds;
                ldsm_x4(bh, bb);
                ldsm_x4(bl, bb + (BLO_OFF - BHI_OFF));
                const int n0 = nc * 2, n1 = nc * 2 + 1;
                mma16816(acc[0][n0], ah0, bh);
                mma16816(acc[1][n0], ah1, bh);
                mma16816(acc[0][n1], ah0, bh + 2);
                mma16816(acc[1][n1], ah1, bh + 2);
                mma16816(acc[0][n0], ah0, bl);
                mma16816(acc[1][n0], ah1, bl);
                mma16816(acc[0][n1], ah0, bl + 2);
                mma16816(acc[1][n1], ah1, bl + 2);
                mma16816(acc[0][n0], al0, bh);
                mma16816(acc[1][n0], al1, bh);
                mma16816(acc[0][n1], al0, bh + 2);
                mma16816(acc[1][n1], al1, bh + 2);
            }
        }
    }

    // Zp: combine the two half-row threads
    float zsum = zacc + __shfl_xor_sync(0xffffffffu, zacc, 1);
    if (half == 0) g_Zp[sp * N_ + grow] = zsum;

    // epilogue: fragment -> g_hp partial
    const int er0 = rb * RT + wrow * 32 + (lane >> 2);
    const int ec0 = wcol * 64 + 2 * (lane & 3);
#pragma unroll
    for (int m = 0; m < 2; ++m) {
#pragma unroll
        for (int n = 0; n < 8; ++n) {
            size_t base = ((size_t)sp * N_ + er0 + m * 16) * OF + ec0 + n * 8;
            *reinterpret_cast<float2*>(g_hp + base) = make_float2(acc[m][n][0], acc[m][n][1]);
            *reinterpret_cast<float2*>(g_hp + base + (size_t)8 * OF) = make_float2(acc[m][n][2], acc[m][n][3]);
        }
    }
}

// ============================================================
// Kernel 5: invZ[i] = 1 / sum_splits Zp
// ============================================================
__global__ void k_invz() {
    int i = blockIdx.x * 1024 + threadIdx.x;
    float z = 0.f;
#pragma unroll
    for (int s = 0; s < NSPLIT; ++s) z += g_Zp[s * N_ + i];
    g_invZ[i] = 1.0f / z;
}

// ============================================================
// Kernel 6: h_prime = (sum_splits hp_part) * invZ  -> d_out[0:N*OF]
// ============================================================
__global__ void k_merge(float* __restrict__ out) {
    size_t idx = (size_t)blockIdx.x * 1024 + threadIdx.x;
    int row = (int)(idx >> 7);
    float s = 0.f;
#pragma unroll
    for (int p = 0; p < NSPLIT; ++p) s += g_hp[(size_t)p * N_ * OF + idx];
    out[idx] = s * g_invZ[row];
}

// ============================================================
// Kernel 7: attention from bitmask + separable exp (write-bound)
//   attention_ij = bit ? (E_j>=G_i ? C_i*E_j : D_i*F_j)*invZ_i : 0
// ============================================================
__global__ __launch_bounds__(256) void k_attn(float* __restrict__ out) {
    __shared__ uint32_t msk[N_ / 32];   // 1.5 KB
    const int row = blockIdx.x;
    const int t = threadIdx.x;
    for (int i = t; i < N_ / 32; i += 256)
        msk[i] = g_mask[(size_t)row * (N_ / 32) + i];

    const float sv = g_src[row];
    float e0 = sv + g_Tmax;
    const float m  = fmaxf(e0, SLOPE * e0);
    const float iz = g_invZ[row];
    const float Cc = __expf(e0 - m) * iz;
    const float Dc = __expf(SLOPE * e0 - m) * iz;
    const float Gc = __expf(-e0);
    __syncthreads();

    const float4* ef4 = reinterpret_cast<const float4*>(g_EF);
    float4* orow = reinterpret_cast<float4*>(out + (size_t)row * N_);
#pragma unroll
    for (int it = 0; it < N_ / 4 / 256; ++it) {
        int j4 = it * 256 + t;                        // j = 4*j4
        float4 efA = __ldg(ef4 + j4 * 2);             // (E,F) j0,j1
        float4 efB = __ldg(ef4 + j4 * 2 + 1);         // (E,F) j2,j3
        uint32_t w = msk[j4 >> 3] >> ((j4 & 7) * 4);  // 4 bits
        float4 o;
        bool pos; float p;
        pos = efA.x >= Gc; p = (pos ? Cc : Dc) * (pos ? efA.x : efA.y); o.x = (w & 1u) ? p : 0.f;
        pos = efA.z >= Gc; p = (pos ? Cc : Dc) * (pos ? efA.z : efA.w); o.y = (w & 2u) ? p : 0.f;
        pos = efB.x >= Gc; p = (pos ? Cc : Dc) * (pos ? efB.x : efB.y); o.z = (w & 4u) ? p : 0.f;
        pos = efB.z >= Gc; p = (pos ? Cc : Dc) * (pos ? efB.z : efB.w); o.w = (w & 8u) ? p : 0.f;
        orow[j4] = o;
    }
}

// ============================================================
extern "C" void kernel_launch(void* const* d_in, const int* in_sizes, int n_in,
                              void* d_out, int out_size) {
    const float* h   = (const float*)d_in[0];
    const int*   adj = (const int*)d_in[1];
    const float* W   = (const float*)d_in[2];
    const float* a   = (const float*)d_in[3];
    float* out = (float*)d_out;

    cudaFuncSetAttribute(k_main, cudaFuncAttributeMaxDynamicSharedMemorySize, DYN_SMEM);

    k_ht<<<N_ / 64, 256>>>(h, W);
    k_srctgt<<<N_ / 8, 256>>>(a);
    k_tmax<<<1, 1024>>>();
    k_ef<<<N_ / 256, 256>>>();
    k_htT<<<N_ / 32, 256>>>();
    k_main<<<(N_ / RT) * NSPLIT, 256, DYN_SMEM>>>(adj);
    k_invz<<<N_ / 1024, 1024>>>();
    k_merge<<<(N_ * OF) / 1024, 1024>>>(out);
    k_attn<<<N_, 256>>>(out + (size_t)N_ * OF);
}

// round 11
// speedup vs baseline: 1.9482x; 1.0469x over previous
#include <cuda_runtime.h>
#include <cstdint>
#include <cstddef>

// GraphAttentionLayer: N=12288, IN_F=256, OUT_F=128
// out = [h_prime (N*128 f32) | attention (N*N f32)]

constexpr int N_  = 12288;
constexpr int INF = 256;
constexpr int OF  = 128;
constexpr float SLOPE = 0.2f;

// ---- k_main tiling (warp-level single-pass tf32 mma.sync) ----
constexpr int RT = 128;             // rows per CTA (MMA M)
constexpr int KT = 32;              // j per tile
constexpr int NSPLIT = 3;           // j split: 96*3 = 288 CTAs = one occ-2 wave
constexpr int JSEG = N_ / NSPLIT;   // 4096
constexpr int NTILE = JSEG / KT;    // 128

// smem stage: rows of 32 f32 + 4 f32 pad = 144B (16B-aligned, conflict-free
// fragment loads: bank = (4*row + 8*t4) mod 32, distinct within each
// LDS.128 quad-phase). j-dim stored k-interleaved: pos(j) = (j&3)*8 + (j>>2)
// so every tf32 fragment (all 4 ksteps) is 8 consecutive f32 = 2x LDS.128.
constexpr int ROWB = 144;
constexpr int A_OFF = 0;                     // p    [128 r x 32 f32]
constexpr int B_OFF = 128 * ROWB;            // htT  [128 c x 32 f32]
constexpr int STAGE_BYTES = 2 * 128 * ROWB;  // 36864
constexpr int DYN_SMEM = 2 * STAGE_BYTES;    // 73728

// ---- scratch (static device arrays; no allocation allowed) ----
__device__ float g_ht[(size_t)N_ * OF];              // h @ W               6 MB
__device__ float g_htT_perm[(size_t)OF * N_];        // h_t^T tf32, k-perm  6 MB
__device__ float g_src[N_];
__device__ float g_tgt[N_];
__device__ float g_Tmax;
__device__ float2 g_EF[N_];                          // (E_j, F_j) tables  96 KB
__device__ uint32_t g_mask[(size_t)N_ * N_ / 32];    // adj bitmask        18.9 MB
__device__ float g_Zp[NSPLIT * N_];                  // partial Z per split
__device__ float g_hp[(size_t)NSPLIT * N_ * OF];     // partial h_prime    18.9 MB
__device__ float g_invZ[N_];

// ============================================================
// helpers
// ============================================================
__device__ __forceinline__ uint32_t cvta_smem(const void* p) {
    uint32_t a;
    asm("{ .reg .u64 t; cvta.to.shared.u64 t, %1; cvt.u32.u64 %0, t; }" : "=r"(a) : "l"(p));
    return a;
}
__device__ __forceinline__ uint32_t f2tf32(float v) {
    uint32_t u;
    asm("cvt.rna.tf32.f32 %0, %1;" : "=r"(u) : "f"(v));
    return u;
}
__device__ __forceinline__ void lds128(uint32_t r[4], uint32_t addr) {
    asm volatile("ld.shared.v4.b32 {%0,%1,%2,%3}, [%4];"
                 : "=r"(r[0]), "=r"(r[1]), "=r"(r[2]), "=r"(r[3]) : "r"(addr));
}
// mma m16n8k8 tf32 -> f32, D += A*B
__device__ __forceinline__ void mma_tf32(float c[4], uint32_t a0, uint32_t a1,
                                         uint32_t a2, uint32_t a3,
                                         uint32_t b0, uint32_t b1) {
    asm volatile(
        "mma.sync.aligned.m16n8k8.row.col.f32.tf32.tf32.f32 "
        "{%0,%1,%2,%3}, {%4,%5,%6,%7}, {%8,%9}, {%0,%1,%2,%3};"
        : "+f"(c[0]), "+f"(c[1]), "+f"(c[2]), "+f"(c[3])
        : "r"(a0), "r"(a1), "r"(a2), "r"(a3), "r"(b0), "r"(b1));
}
__device__ __forceinline__ void cp_async16(uint32_t smem_dst, const void* gsrc) {
    asm volatile("cp.async.ca.shared.global [%0], [%1], 16;"
                 :: "r"(smem_dst), "l"(gsrc) : "memory");
}

// ============================================================
// Kernel 1: h_t = h @ W; epilogue writes k-interleaved tf32 h_t^T
// ============================================================
__global__ __launch_bounds__(256) void k_ht(const float* __restrict__ h, const float* __restrict__ W) {
    extern __shared__ float sm[];
    float* As = sm;             // 64*32
    float* Bs = sm + 2048;      // 32*128
    const int t = threadIdx.x, tx = t & 31, ty = t >> 5;
    const int r0 = blockIdx.x * 64;
    float4 acc[8];
#pragma unroll
    for (int r = 0; r < 8; ++r) acc[r] = make_float4(0.f, 0.f, 0.f, 0.f);

    for (int k0 = 0; k0 < INF; k0 += 32) {
#pragma unroll
        for (int k = 0; k < 2; ++k) {
            int id = t + k * 256;
            int row = id >> 3, c4 = id & 7;
            reinterpret_cast<float4*>(As)[id] =
                *reinterpret_cast<const float4*>(h + (size_t)(r0 + row) * INF + k0 + c4 * 4);
        }
#pragma unroll
        for (int k = 0; k < 4; ++k) {
            int id = t + k * 256;
            int row = id >> 5, c4 = id & 31;
            reinterpret_cast<float4*>(Bs)[id] =
                *reinterpret_cast<const float4*>(W + (size_t)(k0 + row) * OF + c4 * 4);
        }
        __syncthreads();
#pragma unroll
        for (int kk = 0; kk < 32; ++kk) {
            float4 b = reinterpret_cast<const float4*>(Bs)[kk * 32 + tx];
#pragma unroll
            for (int r = 0; r < 8; ++r) {
                float a = As[(ty * 8 + r) * 32 + kk];
                acc[r].x = fmaf(a, b.x, acc[r].x);
                acc[r].y = fmaf(a, b.y, acc[r].y);
                acc[r].z = fmaf(a, b.z, acc[r].z);
                acc[r].w = fmaf(a, b.w, acc[r].w);
            }
        }
        __syncthreads();
    }
#pragma unroll
    for (int r = 0; r < 8; ++r)
        *reinterpret_cast<float4*>(&g_ht[(size_t)(r0 + ty * 8 + r) * OF + tx * 4]) = acc[r];

    // ---- epilogue: transpose to ts[jl][c], then write tf32-rounded,
    //      k-interleaved h_t^T (pos(j) = (j&3)*8 + (j>>2) within 32-j tiles)
    __syncthreads();
    float* ts = sm;                         // 64 x 136 f32 (reuse)
#pragma unroll
    for (int r = 0; r < 8; ++r) {
        int jl = ty * 8 + r;
        *reinterpret_cast<float4*>(&ts[jl * 136 + tx * 4]) = acc[r];
    }
    __syncthreads();
    const int lane = tx;
    for (int seg = ty; seg < 256; seg += 8) {
        int c = seg >> 1, grp = seg & 1;
        int jl = grp * 32 + ((lane & 7) << 2) + (lane >> 3);   // j(pos=lane)
        float v = ts[jl * 136 + c];
        g_htT_perm[(size_t)c * N_ + r0 + grp * 32 + lane] = __uint_as_float(f2tf32(v));
    }
}

// ============================================================
// Kernel 2: src = h_t @ a[:128], tgt = h_t @ a[128:]
// ============================================================
__global__ __launch_bounds__(256) void k_srctgt(const float* __restrict__ a) {
    const int t = threadIdx.x;
    const int lane = t & 31;
    const int row = blockIdx.x * 8 + (t >> 5);
    float4 hv = *reinterpret_cast<const float4*>(g_ht + (size_t)row * OF + lane * 4);
    float4 a1 = *reinterpret_cast<const float4*>(a + lane * 4);
    float4 a2 = *reinterpret_cast<const float4*>(a + OF + lane * 4);
    float s1 = hv.x * a1.x + hv.y * a1.y + hv.z * a1.z + hv.w * a1.w;
    float s2 = hv.x * a2.x + hv.y * a2.y + hv.z * a2.z + hv.w * a2.w;
#pragma unroll
    for (int off = 16; off > 0; off >>= 1) {
        s1 += __shfl_xor_sync(0xffffffffu, s1, off);
        s2 += __shfl_xor_sync(0xffffffffu, s2, off);
    }
    if (lane == 0) { g_src[row] = s1; g_tgt[row] = s2; }
}

// ============================================================
// Kernel 3: Tmax = max(tgt), then EF tables (merged, single block)
//   E_j = exp(tgt_j - Tmax), F_j = exp(0.2*(tgt_j - Tmax))
// ============================================================
__global__ void k_tmaxef() {
    __shared__ float red[1024];
    const int t = threadIdx.x;
    float m = -3.402823466e38f;
    for (int i = t; i < N_; i += 1024) m = fmaxf(m, g_tgt[i]);
    red[t] = m;
    __syncthreads();
    for (int s = 512; s > 0; s >>= 1) {
        if (t < s) red[t] = fmaxf(red[t], red[t + s]);
        __syncthreads();
    }
    float Tm = red[0];
    if (t == 0) g_Tmax = Tm;
    for (int j = t; j < N_; j += 1024) {
        float tm = g_tgt[j] - Tm;
        g_EF[j] = make_float2(__expf(tm), __expf(0.2f * tm));
    }
}

// ============================================================
// Kernel 4 (main): per (128-row block, 1/NSPLIT of columns):
//   p_ij = adj ? (E_j>=G_i ? C_i*E_j : D_i*F_j) : 0
//   Zp[i]  = sum_j p_ij            (register accumulation)
//   hp[i]  = sum_j p_ij * h_t[j]   (single-pass tf32 mma.sync)
//   g_mask = packed adj bits
// 8 warps in 4x2 grid: warp tile 32 rows x 64 cols.
// Double-buffered stage; B via cp.async overlapped with phase A.
// ============================================================
__global__ __launch_bounds__(256, 2) void k_main(const int* __restrict__ adj) {
    extern __shared__ char smem[];
    const uint32_t sbase = cvta_smem(smem);

    const int t = threadIdx.x;
    const int lane = t & 31, wid = t >> 5;
    const int rb = blockIdx.x / NSPLIT;     // row block 0..95
    const int sp = blockIdx.x % NSPLIT;     // j split 0..2
    const int jbase = sp * JSEG;

    // phase-A identity: 2 threads per row, 16 j each
    const int row = t >> 1, half = t & 1;
    const int grow = rb * RT + row;
    const float srcv = g_src[grow];
    float e0 = srcv + g_Tmax;
    const float mv = fmaxf(e0, SLOPE * e0);
    const float Cc = __expf(e0 - mv);
    const float Dc = __expf(SLOPE * e0 - mv);
    const float Gc = __expf(-e0);
    float zacc = 0.f;
    const uint32_t a_row_base = sbase + A_OFF + (uint32_t)row * ROWB;

    // B staging via cp.async: thread -> row c = t>>1, 4 chunks of 16B
    const int bc = t >> 1, bq0 = (t & 1) * 4;

    // fragment identities
    const int wrow = wid >> 1, wcol = wid & 1;          // 4x2 warp grid
    const int fg = lane >> 2, t4 = lane & 3;
    const uint32_t a_frag = A_OFF + (uint32_t)(wrow * 32 + fg) * ROWB + t4 * 32;
    const uint32_t b_frag = B_OFF + (uint32_t)(wcol * 64 + fg) * ROWB + t4 * 32;

    float acc[2][8][4];
#pragma unroll
    for (int m = 0; m < 2; ++m)
#pragma unroll
        for (int n = 0; n < 8; ++n)
#pragma unroll
            for (int k = 0; k < 4; ++k) acc[m][n][k] = 0.f;

    // prefetch adj for tile 0
    int4 padj[4];
    {
        const int4* ap = reinterpret_cast<const int4*>(adj + (size_t)grow * N_ + jbase + half * 16);
#pragma unroll
        for (int i = 0; i < 4; ++i) padj[i] = ap[i];
    }

    uint32_t mw[4];     // packed mask words, flushed every 4 tiles (half==0)

    for (int tt = 0; tt < NTILE; ++tt) {
        const uint32_t stage = sbase + (uint32_t)(tt & 1) * STAGE_BYTES;
        const int j0 = jbase + tt * KT;

        // ---- B tile: cp.async (overlaps with phase A below) ----
        {
            const float* src = g_htT_perm + (size_t)bc * N_ + j0 + bq0 * 4;
            uint32_t dst = stage + B_OFF + bc * ROWB + bq0 * 16;
#pragma unroll
            for (int q = 0; q < 4; ++q)
                cp_async16(dst + q * 16, src + q * 4);
            asm volatile("cp.async.commit_group;" ::: "memory");
        }

        // ---- phase A: p (f32) -> tf32, k-interleaved store + mask bits ----
        {
            const float4* ef4 = reinterpret_cast<const float4*>(g_EF + j0 + half * 16);
            uint32_t mbits = 0;
#pragma unroll
            for (int c4 = 0; c4 < 4; ++c4) {
                const int* av = reinterpret_cast<const int*>(&padj[c4]);
                float4 efA = ef4[c4 * 2];
                float4 efB = ef4[c4 * 2 + 1];
                float Ev[4] = {efA.x, efA.z, efB.x, efB.z};
                float Fv[4] = {efA.y, efA.w, efB.y, efB.w};
#pragma unroll
                for (int u = 0; u < 4; ++u) {
                    bool pos = Ev[u] >= Gc;
                    float p  = (pos ? Cc : Dc) * (pos ? Ev[u] : Fv[u]);
                    bool on  = av[u] > 0;
                    p = on ? p : 0.f;
                    mbits |= (on ? 1u : 0u) << (c4 * 4 + u);
                    zacc += p;
                    int jl = half * 16 + c4 * 4 + u;
                    int pp = ((jl & 3) << 3) + (jl >> 2);
                    uint32_t addr = (stage - sbase) + a_row_base + pp * 4;
                    asm volatile("st.shared.b32 [%0], %1;" :: "r"(addr), "r"(f2tf32(p)));
                }
            }
            uint32_t other = __shfl_xor_sync(0xffffffffu, mbits, 1);
            mw[tt & 3] = half ? ((mbits << 16) | other) : (mbits | (other << 16));
            if ((tt & 3) == 3 && half == 0) {
                *reinterpret_cast<uint4*>(
                    g_mask + (size_t)grow * (N_ / 32) + (jbase >> 5) + (tt - 3)) =
                    make_uint4(mw[0], mw[1], mw[2], mw[3]);
            }
        }

        asm volatile("cp.async.wait_group 0;" ::: "memory");
        __syncthreads();

        // ---- prefetch adj for next tile (regs only, no hazard) ----
        if (tt + 1 < NTILE) {
            const int4* ap = reinterpret_cast<const int4*>(
                adj + (size_t)grow * N_ + jbase + (tt + 1) * KT + half * 16);
#pragma unroll
            for (int i = 0; i < 4; ++i) padj[i] = ap[i];
        }

        // ---- phase B: single-pass tf32 mma ----
        // A fragments: per mi: rows fg, fg+8 -> (a0,a2)/(a1,a3) pairs, all 4 ksteps
        uint32_t aF[2][2][8];   // [mi][rowhalf][2*ks + (0:a0/a1, 1:a2/a3)]
#pragma unroll
        for (int mi = 0; mi < 2; ++mi) {
#pragma unroll
            for (int rh = 0; rh < 2; ++rh) {
                uint32_t ab = stage + a_frag + (uint32_t)(mi * 16 + rh * 8) * ROWB;
                lds128(&aF[mi][rh][0], ab);
                lds128(&aF[mi][rh][4], ab + 16);
            }
        }
#pragma unroll
        for (int nc = 0; nc < 8; ++nc) {
            uint32_t bF[8];
            uint32_t bb = stage + b_frag + (uint32_t)(nc * 8) * ROWB;
            lds128(&bF[0], bb);
            lds128(&bF[4], bb + 16);
#pragma unroll
            for (int ks = 0; ks < 4; ++ks) {
#pragma unroll
                for (int mi = 0; mi < 2; ++mi) {
                    mma_tf32(acc[mi][nc],
                             aF[mi][0][2 * ks], aF[mi][1][2 * ks],
                             aF[mi][0][2 * ks + 1], aF[mi][1][2 * ks + 1],
                             bF[2 * ks], bF[2 * ks + 1]);
                }
            }
        }
    }

    // Zp: combine the two half-row threads
    float zsum = zacc + __shfl_xor_sync(0xffffffffu, zacc, 1);
    if (half == 0) g_Zp[sp * N_ + grow] = zsum;

    // epilogue: fragment -> g_hp partial
    const int er0 = rb * RT + wrow * 32 + fg;
    const int ec0 = wcol * 64 + 2 * t4;
#pragma unroll
    for (int mi = 0; mi < 2; ++mi) {
#pragma unroll
        for (int nc = 0; nc < 8; ++nc) {
            size_t base = ((size_t)sp * N_ + er0 + mi * 16) * OF + ec0 + nc * 8;
            *reinterpret_cast<float2*>(g_hp + base) = make_float2(acc[mi][nc][0], acc[mi][nc][1]);
            *reinterpret_cast<float2*>(g_hp + base + (size_t)8 * OF) = make_float2(acc[mi][nc][2], acc[mi][nc][3]);
        }
    }
}

// ============================================================
// Kernel 5: invZ[i] = 1 / sum_splits Zp
// ============================================================
__global__ void k_invz() {
    int i = blockIdx.x * 1024 + threadIdx.x;
    float z = 0.f;
#pragma unroll
    for (int s = 0; s < NSPLIT; ++s) z += g_Zp[s * N_ + i];
    g_invZ[i] = 1.0f / z;
}

// ============================================================
// Kernel 6: h_prime = (sum_splits hp_part) * invZ  -> d_out[0:N*OF]
// ============================================================
__global__ void k_merge(float* __restrict__ out) {
    size_t idx = (size_t)blockIdx.x * 1024 + threadIdx.x;
    int row = (int)(idx >> 7);
    float s = 0.f;
#pragma unroll
    for (int p = 0; p < NSPLIT; ++p) s += g_hp[(size_t)p * N_ * OF + idx];
    out[idx] = s * g_invZ[row];
}

// ============================================================
// Kernel 7: attention from bitmask + separable exp (write-bound)
// ============================================================
__global__ __launch_bounds__(256) void k_attn(float* __restrict__ out) {
    __shared__ uint32_t msk[N_ / 32];   // 1.5 KB
    const int row = blockIdx.x;
    const int t = threadIdx.x;
    for (int i = t; i < N_ / 32; i += 256)
        msk[i] = g_mask[(size_t)row * (N_ / 32) + i];

    const float sv = g_src[row];
    float e0 = sv + g_Tmax;
    const float m  = fmaxf(e0, SLOPE * e0);
    const float iz = g_invZ[row];
    const float Cc = __expf(e0 - m) * iz;
    const float Dc = __expf(SLOPE * e0 - m) * iz;
    const float Gc = __expf(-e0);
    __syncthreads();

    const float4* ef4 = reinterpret_cast<const float4*>(g_EF);
    float4* orow = reinterpret_cast<float4*>(out + (size_t)row * N_);
#pragma unroll
    for (int it = 0; it < N_ / 4 / 256; ++it) {
        int j4 = it * 256 + t;                        // j = 4*j4
        float4 efA = __ldg(ef4 + j4 * 2);
        float4 efB = __ldg(ef4 + j4 * 2 + 1);
        uint32_t w = msk[j4 >> 3] >> ((j4 & 7) * 4);
        float4 o;
        bool pos; float p;
        pos = efA.x >= Gc; p = (pos ? Cc : Dc) * (pos ? efA.x : efA.y); o.x = (w & 1u) ? p : 0.f;
        pos = efA.z >= Gc; p = (pos ? Cc : Dc) * (pos ? efA.z : efA.w); o.y = (w & 2u) ? p : 0.f;
        pos = efB.x >= Gc; p = (pos ? Cc : Dc) * (pos ? efB.x : efB.y); o.z = (w & 4u) ? p : 0.f;
        pos = efB.z >= Gc; p = (pos ? Cc : Dc) * (pos ? efB.z : efB.w); o.w = (w & 8u) ? p : 0.f;
        orow[j4] = o;
    }
}

// ============================================================
extern "C" void kernel_launch(void* const* d_in, const int* in_sizes, int n_in,
                              void* d_out, int out_size) {
    const float* h   = (const float*)d_in[0];
    const int*   adj = (const int*)d_in[1];
    const float* W   = (const float*)d_in[2];
    const float* a   = (const float*)d_in[3];
    float* out = (float*)d_out;

    cudaFuncSetAttribute(k_main, cudaFuncAttributeMaxDynamicSharedMemorySize, DYN_SMEM);

    constexpr int HT_SMEM = 64 * 136 * 4;   // 34816 (>= As+Bs 24576)

    k_ht<<<N_ / 64, 256, HT_SMEM>>>(h, W);        // launch 1
    k_srctgt<<<N_ / 8, 256>>>(a);                 // launch 2
    k_tmaxef<<<1, 1024>>>();                      // launch 3
    k_main<<<(N_ / RT) * NSPLIT, 256, DYN_SMEM>>>(adj);   // launch 4 (ncu slot)
    k_invz<<<N_ / 1024, 1024>>>();                // launch 5
    k_merge<<<(N_ * OF) / 1024, 1024>>>(out);     // launch 6
    k_attn<<<N_, 256>>>(out + (size_t)N_ * OF);   // launch 7
}